// round 7
// baseline (speedup 1.0000x reference)
#include <cuda_runtime.h>

// AttentionStem: per-pixel 4x4 local window attention. B=4, IC=3, OC=64, H=W=128.
// R7: 2 vertically-adjacent pixels per thread (shared window rows: 10 packed
//     pairs instead of 16), halving per-channel uniform overhead (wv LDS,
//     kw/qw, loop control) and doubling exp-chain ILP. 128 thr/block, grid 1024.

typedef unsigned long long u64;

#define LOG2E 1.4426950408889634f

__device__ __forceinline__ u64 pk2(float lo, float hi) {
    u64 r; asm("mov.b64 %0,{%1,%2};" : "=l"(r) : "f"(lo), "f"(hi)); return r;
}
__device__ __forceinline__ void upk2(u64 a, float& lo, float& hi) {
    asm("mov.b64 {%0,%1},%2;" : "=f"(lo), "=f"(hi) : "l"(a));
}
__device__ __forceinline__ u64 fma2_(u64 a, u64 b, u64 c) {
    u64 r; asm("fma.rn.f32x2 %0,%1,%2,%3;" : "=l"(r) : "l"(a), "l"(b), "l"(c)); return r;
}
__device__ __forceinline__ u64 mul2_(u64 a, u64 b) {
    u64 r; asm("mul.rn.f32x2 %0,%1,%2;" : "=l"(r) : "l"(a), "l"(b)); return r;
}
__device__ __forceinline__ u64 add2_(u64 a, u64 b) {
    u64 r; asm("add.rn.f32x2 %0,%1,%2;" : "=l"(r) : "l"(a), "l"(b)); return r;
}
__device__ __forceinline__ float ex2_(float x) {
    float r; asm("ex2.approx.f32 %0,%1;" : "=f"(r) : "f"(x)); return r;
}
__device__ __forceinline__ float lo32(u64 a) {
    return __int_as_float((int)(unsigned)a);
}

// Precomputed: mixed value weights (u64-packed pairs) and folded q/k weights.
__device__ u64    g_wv[64 * 24];   // [o][c][p], float view [o*48 + c*16 + ij]
__device__ float4 g_kw[64];
__device__ float4 g_qw[64];        // pre-scaled by LOG2E

__global__ void prep_kernel(const float* __restrict__ key_w,
                            const float* __restrict__ query_w,
                            const float* __restrict__ value_w,
                            const float* __restrict__ emb_a,
                            const float* __restrict__ emb_b,
                            const float* __restrict__ emb_mix) {
    __shared__ float sh_lab[32];   // la: [i*4+m], lb: [16 + j*4+m]
    __shared__ float sh_emb[4][16];
    int t = threadIdx.x;

    // Stage 1: la/lb dots, 4 lanes per output, shfl-reduced.
    {
        int outi = t >> 2;                 // 0..31: ab*16 + i4*4 + m
        int chunk = t & 3;
        int m = outi & 3, i4 = (outi >> 2) & 3, ab = outi >> 4;
        const float* e = ab ? emb_b : emb_a;
        float s = 0.f;
#pragma unroll
        for (int oo = 0; oo < 16; oo++) {
            int o = chunk * 16 + oo;
            s += emb_mix[m * 64 + o] * e[o * 4 + i4];
        }
        s += __shfl_xor_sync(0xffffffffu, s, 1);
        s += __shfl_xor_sync(0xffffffffu, s, 2);
        if (chunk == 0) sh_lab[outi] = s;
    }
    __syncthreads();

    // Stage 2: softmax over m per window position.
    if (t < 16) {
        int i = t >> 2, j = t & 3;
        float lg[4];
#pragma unroll
        for (int m = 0; m < 4; m++)
            lg[m] = sh_lab[(i << 2) + m] + sh_lab[16 + (j << 2) + m];
        float mx = fmaxf(fmaxf(lg[0], lg[1]), fmaxf(lg[2], lg[3]));
        float e[4], s = 0.f;
#pragma unroll
        for (int m = 0; m < 4; m++) { e[m] = __expf(lg[m] - mx); s += e[m]; }
        float inv = __fdividef(1.f, s);
#pragma unroll
        for (int m = 0; m < 4; m++) sh_emb[m][t] = e[m] * inv;
    }
    __syncthreads();

    // Stage 3: mixed value weights, all 64 channels (3072 floats, 24/thread).
    float* wvf = (float*)g_wv;
    for (int f = t; f < 3072; f += 128) {
        int o = f / 48, r = f % 48, c = r >> 4, ij = r & 15;
        float acc = 0.f;
#pragma unroll
        for (int m = 0; m < 4; m++)
            acc += sh_emb[m][ij] * value_w[(m * 64 + o) * 3 + c];
        wvf[f] = acc;
    }
    // Stage 3b: packed k/q weights.
    if (t < 64) {
        g_kw[t] = make_float4(key_w[t * 3], key_w[t * 3 + 1], key_w[t * 3 + 2], 0.f);
        g_qw[t] = make_float4(query_w[t * 3] * LOG2E,
                              query_w[t * 3 + 1] * LOG2E,
                              query_w[t * 3 + 2] * LOG2E, 0.f);
    }
}

__global__ __launch_bounds__(128)
void attn_kernel(const float* __restrict__ x, float* __restrict__ out) {
    __shared__ float  sh_x[3][5][132];   // [c][tile row][padded col]
    __shared__ float4 sh_kw[16];
    __shared__ float4 sh_qw[16];
    __shared__ u64    sh_wv[16 * 24];    // [o][c][p]

    int tid = threadIdx.x;
    int oq = blockIdx.x & 3;             // quarter of the 64 channels
    int rest = blockIdx.x >> 2;
    int b = rest >> 6;
    int hp = rest & 63;
    int h0 = hp * 2;                     // this block: output rows h0, h0+1

    // Copy-only prologue: 5-row x tile (h0-2 .. h0+2) + wv + kw/qw; 1 barrier.
    for (int idx = tid; idx < 3 * 5 * 132; idx += 128) {
        int c = idx / 660, rem = idx % 660, r = rem / 132, cc = rem % 132;
        int hr = h0 - 2 + r, wc = cc - 2;
        float v = 0.f;
        if (hr >= 0 && hr < 128 && wc >= 0 && wc < 128)
            v = x[((b * 3 + c) * 128 + hr) * 128 + wc];
        sh_x[c][r][cc] = v;
    }
    // wv slice: 384 u64 = 192 ulonglong2 over 128 threads.
    {
        const ulonglong2* src = (const ulonglong2*)(g_wv + oq * 384);
        ulonglong2* dst = (ulonglong2*)sh_wv;
        dst[tid] = src[tid];
        if (tid < 64) dst[128 + tid] = src[128 + tid];
    }
    if (tid < 16) {
        sh_kw[tid] = g_kw[oq * 16 + tid];
        sh_qw[tid] = g_qw[oq * 16 + tid];
    }
    __syncthreads();

    int w = tid;

    // Shared window rows: 10 packed pairs per channel (tile rows 0..4, j0 in {0,2}).
    // Pixel0 (row h0)   uses tile pairs p   (p = 0..7).
    // Pixel1 (row h0+1) uses tile pairs p+2.
    u64 wp0[10], wp1[10], wp2[10];
#pragma unroll
    for (int t = 0; t < 10; t++) {
        int i = t >> 1, j0 = (t & 1) * 2;
        wp0[t] = pk2(sh_x[0][i][w + j0], sh_x[0][i][w + j0 + 1]);
        wp1[t] = pk2(sh_x[1][i][w + j0], sh_x[1][i][w + j0 + 1]);
        wp2[t] = pk2(sh_x[2][i][w + j0], sh_x[2][i][w + j0 + 1]);
    }

    float* outp = out + (((b * 64) + oq * 16) * 128 + h0) * 128 + w;

#pragma unroll 1
    for (int o = 0; o < 16; o++) {
        float4 qw = sh_qw[o];
        float4 kw = sh_kw[o];
        // centers: pixel0 = tile pair 5 lo (row 2, col w+2); pixel1 = pair 7 lo.
        float q0 = qw.x * lo32(wp0[5]) + qw.y * lo32(wp1[5]) + qw.z * lo32(wp2[5]);
        float q1 = qw.x * lo32(wp0[7]) + qw.y * lo32(wp1[7]) + qw.z * lo32(wp2[7]);
        float a00 = q0 * kw.x, a01 = q0 * kw.y, a02 = q0 * kw.z;
        float a10 = q1 * kw.x, a11 = q1 * kw.y, a12 = q1 * kw.z;
        u64 k00 = pk2(a00, a00), k01 = pk2(a01, a01), k02 = pk2(a02, a02);
        u64 k10 = pk2(a10, a10), k11 = pk2(a11, a11), k12 = pk2(a12, a12);
        const u64* wvp = sh_wv + o * 24;

        u64 acc0 = 0ull, ss0 = 0ull, acc1 = 0ull, ss1 = 0ull;
#pragma unroll
        for (int pp = 0; pp < 4; pp++) {
            ulonglong2 wv0 = *(const ulonglong2*)(wvp + 2 * pp);
            ulonglong2 wv1 = *(const ulonglong2*)(wvp + 8 + 2 * pp);
            ulonglong2 wv2 = *(const ulonglong2*)(wvp + 16 + 2 * pp);
#pragma unroll
            for (int s = 0; s < 2; s++) {
                int p = 2 * pp + s;
                u64 wvx = s ? wv0.y : wv0.x;
                u64 wvy = s ? wv1.y : wv1.x;
                u64 wvz = s ? wv2.y : wv2.x;
                // pixel0
                {
                    u64 l2 = fma2_(k00, wp0[p], fma2_(k01, wp1[p], mul2_(k02, wp2[p])));
                    float l0, l1; upk2(l2, l0, l1);
                    u64 e2 = pk2(ex2_(l0), ex2_(l1));
                    u64 v2 = fma2_(wvx, wp0[p], fma2_(wvy, wp1[p], mul2_(wvz, wp2[p])));
                    acc0 = fma2_(e2, v2, acc0);
                    ss0  = add2_(e2, ss0);
                }
                // pixel1 (tile pairs shifted by one row = +2)
                {
                    int t = p + 2;
                    u64 l2 = fma2_(k10, wp0[t], fma2_(k11, wp1[t], mul2_(k12, wp2[t])));
                    float l0, l1; upk2(l2, l0, l1);
                    u64 e2 = pk2(ex2_(l0), ex2_(l1));
                    u64 v2 = fma2_(wvx, wp0[t], fma2_(wvy, wp1[t], mul2_(wvz, wp2[t])));
                    acc1 = fma2_(e2, v2, acc1);
                    ss1  = add2_(e2, ss1);
                }
            }
        }
        float a0, a1, s0, s1;
        upk2(acc0, a0, a1);
        upk2(ss0, s0, s1);
        outp[o * 16384] = __fdividef(a0 + a1, s0 + s1);
        upk2(acc1, a0, a1);
        upk2(ss1, s0, s1);
        outp[o * 16384 + 128] = __fdividef(a0 + a1, s0 + s1);
    }
}

extern "C" void kernel_launch(void* const* d_in, const int* in_sizes, int n_in,
                              void* d_out, int out_size) {
    const float* x       = (const float*)d_in[0];
    const float* key_w   = (const float*)d_in[1];
    const float* query_w = (const float*)d_in[2];
    const float* value_w = (const float*)d_in[3];
    const float* emb_a   = (const float*)d_in[4];
    const float* emb_b   = (const float*)d_in[5];
    const float* emb_mix = (const float*)d_in[6];
    float* out = (float*)d_out;

    prep_kernel<<<1, 128>>>(key_w, query_w, value_w, emb_a, emb_b, emb_mix);
    attn_kernel<<<1024, 128>>>(x, out);
}